// round 2
// baseline (speedup 1.0000x reference)
#include <cuda_runtime.h>
#include <cuda_bf16.h>
#include <cstdint>
#include <math.h>

// Problem constants
#define NB    16      // batch
#define LQ    300     // queries
#define CC    256     // channels
#define NHEAD 8
#define NLVL  3
#define NPT   4
#define LV    8400    // sum of h*w
#define HD    32      // head dim

// Scratch (static __device__ arrays; no dynamic allocation allowed)
__device__ float g_v[(size_t)NB * LV * CC];        // projected value, ~137.6 MB
__device__ float g_off[(size_t)NB * LQ * 192];     // sampling offset logits
__device__ float g_attn[(size_t)NB * LQ * 96];     // attention logits
__device__ float g_samp[(size_t)NB * LQ * CC];     // sampled output (pre out-proj)

// ---------------------------------------------------------------------------
// Generic fp32 GEMM: C[M,N] = A[M,K] @ B[K,N] + bias[N]
// BM=128, BN=64, BK=16, TM=8, TN=4, 256 threads.
// Requires K % 16 == 0, N % 4 == 0 (true for all shapes here: N in {256,192,96}).
// ---------------------------------------------------------------------------
#define BM 128
#define BN 64
#define BKK 16
#define TM 8
#define TN 4

__global__ __launch_bounds__(256) void gemm_bias_kernel(
    const float* __restrict__ A, const float* __restrict__ B,
    const float* __restrict__ bias, float* __restrict__ C,
    int M, int N, int K)
{
    __shared__ float As[BKK][BM + 4];   // padded to reduce bank conflicts
    __shared__ float Bs[BKK][BN];

    const int tid = threadIdx.x;
    const int tx = tid % (BN / TN);        // 0..15 (N dir)
    const int ty = tid / (BN / TN);        // 0..15 (M dir)
    const int m0 = blockIdx.y * BM;
    const int n0 = blockIdx.x * BN;

    float acc[TM][TN];
    #pragma unroll
    for (int i = 0; i < TM; i++)
        #pragma unroll
        for (int j = 0; j < TN; j++) acc[i][j] = 0.f;

    for (int k0 = 0; k0 < K; k0 += BKK) {
        // Load A tile (BM x BK) as float4, store transposed into As[k][m]
        #pragma unroll
        for (int i = tid; i < BM * BKK / 4; i += 256) {
            int r  = i >> 2;             // row within tile (0..127)
            int c4 = (i & 3) * 4;        // k offset (0,4,8,12)
            float4 v = make_float4(0.f, 0.f, 0.f, 0.f);
            if (m0 + r < M)
                v = *(const float4*)&A[(size_t)(m0 + r) * K + k0 + c4];
            As[c4 + 0][r] = v.x;
            As[c4 + 1][r] = v.y;
            As[c4 + 2][r] = v.z;
            As[c4 + 3][r] = v.w;
        }
        // Load B tile (BK x BN)
        #pragma unroll
        for (int i = tid; i < BKK * BN / 4; i += 256) {
            int r  = i / (BN / 4);
            int c4 = (i % (BN / 4)) * 4;
            float4 v = make_float4(0.f, 0.f, 0.f, 0.f);
            if (n0 + c4 < N)
                v = *(const float4*)&B[(size_t)(k0 + r) * N + n0 + c4];
            *(float4*)&Bs[r][c4] = v;
        }
        __syncthreads();

        #pragma unroll
        for (int k = 0; k < BKK; k++) {
            float ra[TM], rb[TN];
            #pragma unroll
            for (int i = 0; i < TM; i++) ra[i] = As[k][ty * TM + i];
            #pragma unroll
            for (int j = 0; j < TN; j++) rb[j] = Bs[k][tx * TN + j];
            #pragma unroll
            for (int i = 0; i < TM; i++)
                #pragma unroll
                for (int j = 0; j < TN; j++)
                    acc[i][j] = fmaf(ra[i], rb[j], acc[i][j]);
        }
        __syncthreads();
    }

    // Epilogue: bias + store (float4)
    const int c = n0 + tx * TN;
    if (c < N) {
        float4 bv = *(const float4*)&bias[c];
        #pragma unroll
        for (int i = 0; i < TM; i++) {
            int r = m0 + ty * TM + i;
            if (r >= M) continue;
            float4 v;
            v.x = acc[i][0] + bv.x;
            v.y = acc[i][1] + bv.y;
            v.z = acc[i][2] + bv.z;
            v.w = acc[i][3] + bv.w;
            *(float4*)&C[(size_t)r * N + c] = v;
        }
    }
}

// ---------------------------------------------------------------------------
// Fused softmax + sampling-location + bilinear gather kernel.
// 1 block per (n, q); 256 threads = 8 warps; warp h handles head h; lane = channel d.
// ---------------------------------------------------------------------------
__global__ __launch_bounds__(256) void msda_sample_kernel(
    const float* __restrict__ ref_points,   // (N, Lq, 3, 4)
    float* __restrict__ out)                // g_samp (N*Lq, 256)
{
    const int b = blockIdx.x;               // n*LQ + q
    const int n = b / LQ;
    const int tid = threadIdx.x;
    const int lane = tid & 31;
    const int h = tid >> 5;

    __shared__ float s_aw[96];
    __shared__ float s_gx[96];
    __shared__ float s_gy[96];

    // --- softmax over 12 (l,p) for head h (warp h, lanes 0..11) ---
    {
        float logit = (lane < 12) ? g_attn[(size_t)b * 96 + h * 12 + lane] : -INFINITY;
        float m = logit;
        #pragma unroll
        for (int o = 8; o; o >>= 1) m = fmaxf(m, __shfl_xor_sync(0xffffffffu, m, o, 16));
        float e = (lane < 12) ? expf(logit - m) : 0.f;
        float s = e;
        #pragma unroll
        for (int o = 8; o; o >>= 1) s += __shfl_xor_sync(0xffffffffu, s, o, 16);
        if (lane < 12) s_aw[h * 12 + lane] = e / s;
    }

    // --- sampling locations: tid < 96 covers (h2, l, p) ---
    if (tid < 96) {
        const int h2 = tid / 12;
        const int rem = tid % 12;
        const int l = rem >> 2;
        const int p = rem & 3;
        const float* rp = &ref_points[((size_t)b * NLVL + l) * 4];
        const size_t obase = (size_t)b * 192 + ((size_t)(h2 * NLVL + l) * NPT + p) * 2;
        float ox = g_off[obase + 0];
        float oy = g_off[obase + 1];
        // loc = ref_cxcy + off/P * ref_wh * 0.5 = ref + off * 0.125 * wh
        float lx = rp[0] + ox * 0.125f * rp[2];
        float ly = rp[1] + oy * 0.125f * rp[3];
        const int Wl = (l == 0) ? 80 : (l == 1) ? 40 : 20;
        const int Hl = Wl;
        // pixel coords: gx = loc_x * W - 0.5
        s_gx[tid] = lx * (float)Wl - 0.5f;
        s_gy[tid] = ly * (float)Hl - 0.5f;
    }
    __syncthreads();

    // --- gather + weighted accumulate: warp h, lane = channel d ---
    float acc = 0.f;
    const float* vbase = g_v + (size_t)n * LV * CC + h * HD + lane;

    #pragma unroll
    for (int j = 0; j < 12; j++) {
        const int l = j >> 2;
        const int Wl = (l == 0) ? 80 : (l == 1) ? 40 : 20;
        const int Hl = Wl;
        const int st = (l == 0) ? 0 : (l == 1) ? 6400 : 8000;

        float gx = s_gx[h * 12 + j];
        float gy = s_gy[h * 12 + j];
        float aw = s_aw[h * 12 + j];

        float x0f = floorf(gx), y0f = floorf(gy);
        int x0 = (int)x0f, y0 = (int)y0f;
        float wx = gx - x0f, wy = gy - y0f;

        bool vx0 = (x0 >= 0) && (x0 < Wl);
        bool vx1 = (x0 + 1 >= 0) && (x0 + 1 < Wl);
        bool vy0 = (y0 >= 0) && (y0 < Hl);
        bool vy1 = (y0 + 1 >= 0) && (y0 + 1 < Hl);

        const float* p00 = vbase + ((ptrdiff_t)st + (ptrdiff_t)y0 * Wl + x0) * CC;
        float v00 = (vx0 && vy0) ? p00[0] : 0.f;
        float v01 = (vx1 && vy0) ? p00[CC] : 0.f;
        float v10 = (vx0 && vy1) ? p00[(ptrdiff_t)Wl * CC] : 0.f;
        float v11 = (vx1 && vy1) ? p00[(ptrdiff_t)(Wl + 1) * CC] : 0.f;

        float top = v00 + wx * (v01 - v00);
        float bot = v10 + wx * (v11 - v10);
        acc = fmaf(aw, top + wy * (bot - top), acc);
    }

    out[(size_t)b * CC + h * HD + lane] = acc;
}

// ---------------------------------------------------------------------------
// Launch
// ---------------------------------------------------------------------------
extern "C" void kernel_launch(void* const* d_in, const int* in_sizes, int n_in,
                              void* d_out, int out_size)
{
    const float* query  = (const float*)d_in[0];
    const float* refp   = (const float*)d_in[1];
    const float* value  = (const float*)d_in[2];
    const float* W_off  = (const float*)d_in[3];
    const float* b_off  = (const float*)d_in[4];
    const float* W_attn = (const float*)d_in[5];
    const float* b_attn = (const float*)d_in[6];
    const float* W_val  = (const float*)d_in[7];
    const float* b_val  = (const float*)d_in[8];
    const float* W_out  = (const float*)d_in[9];
    const float* b_out  = (const float*)d_in[10];
    float* out = (float*)d_out;

    // Resolve scratch symbol addresses once (deterministic; capture-safe).
    static float *gv = nullptr, *goff = nullptr, *gattn = nullptr, *gsamp = nullptr;
    if (!gv) {
        cudaGetSymbolAddress((void**)&gv,    g_v);
        cudaGetSymbolAddress((void**)&goff,  g_off);
        cudaGetSymbolAddress((void**)&gattn, g_attn);
        cudaGetSymbolAddress((void**)&gsamp, g_samp);
    }

    const int MQ = NB * LQ;       // 4800
    const int MV = NB * LV;       // 134400

    // 1) value projection: v = value @ W_val + b_val  (dominant GEMM)
    {
        dim3 grid((CC + BN - 1) / BN, (MV + BM - 1) / BM);
        gemm_bias_kernel<<<grid, 256>>>(value, W_val, b_val, gv, MV, CC, CC);
    }
    // 2) offset logits: query @ W_off + b_off
    {
        dim3 grid((192 + BN - 1) / BN, (MQ + BM - 1) / BM);
        gemm_bias_kernel<<<grid, 256>>>(query, W_off, b_off, goff, MQ, 192, CC);
    }
    // 3) attention logits: query @ W_attn + b_attn
    {
        dim3 grid((96 + BN - 1) / BN, (MQ + BM - 1) / BM);
        gemm_bias_kernel<<<grid, 256>>>(query, W_attn, b_attn, gattn, MQ, 96, CC);
    }
    // 4) fused softmax + locations + bilinear sampling
    msda_sample_kernel<<<MQ, 256>>>(refp, gsamp);

    // 5) output projection: out = sampled @ W_out + b_out
    {
        dim3 grid((CC + BN - 1) / BN, (MQ + BM - 1) / BM);
        gemm_bias_kernel<<<grid, 256>>>(gsamp, W_out, b_out, out, MQ, CC, CC);
    }
}

// round 7
// speedup vs baseline: 1.7496x; 1.7496x over previous
#include <cuda_runtime.h>
#include <cuda_bf16.h>
#include <cstdint>
#include <math.h>

// Problem constants
#define NB    16
#define LQ    300
#define CC    256
#define NHEAD 8
#define NLVL  3
#define NPT   4
#define LV    8400
#define HD    32

// Scratch
__device__ float g_v[(size_t)NB * LV * CC];        // projected value (~137.6 MB)
__device__ float g_wt[(size_t)CC * CC];            // W_val^T
__device__ float g_off[(size_t)NB * LQ * 192];
__device__ float g_attn[(size_t)NB * LQ * 96];
__device__ float g_samp[(size_t)NB * LQ * CC];

__device__ __forceinline__ float tf32_rna(float x) {
    uint32_t r;
    asm("cvt.rna.tf32.f32 %0, %1;" : "=r"(r) : "f"(x));
    return __uint_as_float(r);
}

__device__ __forceinline__ void mma_tf32_16x8x8(
    float& d0, float& d1, float& d2, float& d3,
    uint32_t a0, uint32_t a1, uint32_t a2, uint32_t a3,
    uint32_t b0, uint32_t b1)
{
    asm volatile(
        "mma.sync.aligned.m16n8k8.row.col.f32.tf32.tf32.f32 "
        "{%0,%1,%2,%3}, {%4,%5,%6,%7}, {%8,%9}, {%0,%1,%2,%3};"
        : "+f"(d0), "+f"(d1), "+f"(d2), "+f"(d3)
        : "r"(a0), "r"(a1), "r"(a2), "r"(a3), "r"(b0), "r"(b1));
}

// ===========================================================================
// W_val transpose: g_wt[n][k] = W_val[k][n]
// ===========================================================================
__global__ void transpose256_kernel(const float* __restrict__ W, float* __restrict__ WT) {
    __shared__ float t[32][33];
    int x = blockIdx.x * 32 + threadIdx.x;
    int y = blockIdx.y * 32 + threadIdx.y;
    #pragma unroll
    for (int j = 0; j < 32; j += 8)
        t[threadIdx.y + j][threadIdx.x] = W[(y + j) * 256 + x];
    __syncthreads();
    x = blockIdx.y * 32 + threadIdx.x;
    y = blockIdx.x * 32 + threadIdx.y;
    #pragma unroll
    for (int j = 0; j < 32; j += 8)
        WT[(y + j) * 256 + x] = t[threadIdx.x][threadIdx.y + j];
}

// ===========================================================================
// Value projection via mma.sync tf32 (sm_100-safe):
//   g_v[m][n] = sum_k value[m][k] * W[k][n] + b[n]
// Block 128x64, 8 warps (4x2), warp tile 32x32 (2x4 m16n8k8), BK=32.
// Grid: (N/64=4, M/128=1050). M=134400 divisible by 128.
// ===========================================================================
#define SA_STRIDE 36   // padded word stride -> conflict-free fragment LDS
__global__ __launch_bounds__(256) void value_mma_kernel(
    const float* __restrict__ A,      // value (M x 256)
    const float* __restrict__ WT,     // W^T  (256 x 256), WT[n][k]
    const float* __restrict__ bias,   // (256)
    float* __restrict__ C)            // g_v (M x 256)
{
    __shared__ float As[128 * SA_STRIDE];   // 128 rows x 32 k (padded)
    __shared__ float Bs[64 * SA_STRIDE];    // 64 n-rows x 32 k (padded)

    const int tid  = threadIdx.x;
    const int lane = tid & 31;
    const int wid  = tid >> 5;
    const int wr   = wid & 3;          // warp row (M): 4
    const int wc   = wid >> 2;         // warp col (N): 2
    const int gq   = lane >> 2;        // groupID 0..7
    const int tg   = lane & 3;         // thread-in-group 0..3

    const int m0 = blockIdx.y * 128;
    const int n0 = blockIdx.x * 64;

    float acc[2][4][4];
    #pragma unroll
    for (int mt = 0; mt < 2; mt++)
        #pragma unroll
        for (int nt = 0; nt < 4; nt++)
            #pragma unroll
            for (int r = 0; r < 4; r++) acc[mt][nt][r] = 0.f;

    for (int k0 = 0; k0 < 256; k0 += 32) {
        // A tile: 128 rows x 32 floats = 1024 float4, 4 per thread
        #pragma unroll
        for (int i = 0; i < 4; i++) {
            int idx = tid + i * 256;          // 0..1023
            int r = idx >> 3, c4 = idx & 7;
            float4 v = *(const float4*)&A[(size_t)(m0 + r) * 256 + k0 + c4 * 4];
            float* dst = &As[r * SA_STRIDE + c4 * 4];
            dst[0] = tf32_rna(v.x); dst[1] = tf32_rna(v.y);
            dst[2] = tf32_rna(v.z); dst[3] = tf32_rna(v.w);
        }
        // B tile: 64 n-rows x 32 floats = 512 float4, 2 per thread
        #pragma unroll
        for (int i = 0; i < 2; i++) {
            int idx = tid + i * 256;          // 0..511
            int r = idx >> 3, c4 = idx & 7;
            float4 v = *(const float4*)&WT[(size_t)(n0 + r) * 256 + k0 + c4 * 4];
            float* dst = &Bs[r * SA_STRIDE + c4 * 4];
            dst[0] = tf32_rna(v.x); dst[1] = tf32_rna(v.y);
            dst[2] = tf32_rna(v.z); dst[3] = tf32_rna(v.w);
        }
        __syncthreads();

        #pragma unroll
        for (int kk = 0; kk < 4; kk++) {
            const int kb = kk * 8;
            // A fragments: a0:(m=gq,k=tg) a1:(m=gq+8) a2:(k=tg+4) a3:(both)
            uint32_t af[2][4];
            #pragma unroll
            for (int mt = 0; mt < 2; mt++) {
                const float* ab = &As[(wr * 32 + mt * 16 + gq) * SA_STRIDE + kb + tg];
                af[mt][0] = __float_as_uint(ab[0]);
                af[mt][1] = __float_as_uint(ab[8 * SA_STRIDE]);
                af[mt][2] = __float_as_uint(ab[4]);
                af[mt][3] = __float_as_uint(ab[8 * SA_STRIDE + 4]);
            }
            // B fragments: b0:(k=tg, n=gq) b1:(k=tg+4, n=gq)
            uint32_t bf[4][2];
            #pragma unroll
            for (int nt = 0; nt < 4; nt++) {
                const float* bb = &Bs[(wc * 32 + nt * 8 + gq) * SA_STRIDE + kb + tg];
                bf[nt][0] = __float_as_uint(bb[0]);
                bf[nt][1] = __float_as_uint(bb[4]);
            }
            #pragma unroll
            for (int mt = 0; mt < 2; mt++)
                #pragma unroll
                for (int nt = 0; nt < 4; nt++)
                    mma_tf32_16x8x8(acc[mt][nt][0], acc[mt][nt][1],
                                    acc[mt][nt][2], acc[mt][nt][3],
                                    af[mt][0], af[mt][1], af[mt][2], af[mt][3],
                                    bf[nt][0], bf[nt][1]);
        }
        __syncthreads();
    }

    // Epilogue: c0,c1 -> row gq, cols 2*tg,2*tg+1; c2,c3 -> row gq+8
    #pragma unroll
    for (int mt = 0; mt < 2; mt++) {
        #pragma unroll
        for (int nt = 0; nt < 4; nt++) {
            const int col = n0 + wc * 32 + nt * 8 + tg * 2;
            const float bx = bias[col], by = bias[col + 1];
            const int r0 = m0 + wr * 32 + mt * 16 + gq;
            float2 v0 = make_float2(acc[mt][nt][0] + bx, acc[mt][nt][1] + by);
            float2 v1 = make_float2(acc[mt][nt][2] + bx, acc[mt][nt][3] + by);
            *(float2*)&C[(size_t)r0 * 256 + col]       = v0;
            *(float2*)&C[(size_t)(r0 + 8) * 256 + col] = v1;
        }
    }
}

// ===========================================================================
// Generic fp32 GEMM (3 small projections): C = A@B + bias
// ===========================================================================
#define BM 128
#define BN 64
#define BKK 16
#define TM 8
#define TN 4

__global__ __launch_bounds__(256) void gemm_bias_kernel(
    const float* __restrict__ A, const float* __restrict__ B,
    const float* __restrict__ bias, float* __restrict__ C,
    int M, int N, int K)
{
    __shared__ float As[BKK][BM + 4];
    __shared__ float Bs[BKK][BN];

    const int tid = threadIdx.x;
    const int tx = tid % (BN / TN);
    const int ty = tid / (BN / TN);
    const int m0 = blockIdx.y * BM;
    const int n0 = blockIdx.x * BN;

    float acc[TM][TN];
    #pragma unroll
    for (int i = 0; i < TM; i++)
        #pragma unroll
        for (int j = 0; j < TN; j++) acc[i][j] = 0.f;

    for (int k0 = 0; k0 < K; k0 += BKK) {
        #pragma unroll
        for (int i = tid; i < BM * BKK / 4; i += 256) {
            int r = i >> 2, c4 = (i & 3) * 4;
            float4 v = make_float4(0.f, 0.f, 0.f, 0.f);
            if (m0 + r < M) v = *(const float4*)&A[(size_t)(m0 + r) * K + k0 + c4];
            As[c4 + 0][r] = v.x; As[c4 + 1][r] = v.y; As[c4 + 2][r] = v.z; As[c4 + 3][r] = v.w;
        }
        #pragma unroll
        for (int i = tid; i < BKK * BN / 4; i += 256) {
            int r = i / (BN / 4), c4 = (i % (BN / 4)) * 4;
            float4 v = make_float4(0.f, 0.f, 0.f, 0.f);
            if (n0 + c4 < N) v = *(const float4*)&B[(size_t)(k0 + r) * N + n0 + c4];
            *(float4*)&Bs[r][c4] = v;
        }
        __syncthreads();
        #pragma unroll
        for (int k = 0; k < BKK; k++) {
            float ra[TM], rb[TN];
            #pragma unroll
            for (int i = 0; i < TM; i++) ra[i] = As[k][ty * TM + i];
            #pragma unroll
            for (int j = 0; j < TN; j++) rb[j] = Bs[k][tx * TN + j];
            #pragma unroll
            for (int i = 0; i < TM; i++)
                #pragma unroll
                for (int j = 0; j < TN; j++)
                    acc[i][j] = fmaf(ra[i], rb[j], acc[i][j]);
        }
        __syncthreads();
    }
    const int c = n0 + tx * TN;
    if (c < N) {
        float4 bv = *(const float4*)&bias[c];
        #pragma unroll
        for (int i = 0; i < TM; i++) {
            int r = m0 + ty * TM + i;
            if (r >= M) continue;
            float4 v;
            v.x = acc[i][0] + bv.x; v.y = acc[i][1] + bv.y;
            v.z = acc[i][2] + bv.z; v.w = acc[i][3] + bv.w;
            *(float4*)&C[(size_t)r * N + c] = v;
        }
    }
}

// ===========================================================================
// Fused softmax + location + bilinear sampling
// ===========================================================================
__global__ __launch_bounds__(256) void msda_sample_kernel(
    const float* __restrict__ ref_points, float* __restrict__ out)
{
    const int b = blockIdx.x;
    const int n = b / LQ;
    const int tid = threadIdx.x;
    const int lane = tid & 31;
    const int h = tid >> 5;

    __shared__ float s_aw[96];
    __shared__ float s_gx[96];
    __shared__ float s_gy[96];

    {
        float logit = (lane < 12) ? g_attn[(size_t)b * 96 + h * 12 + lane] : -INFINITY;
        float m = logit;
        #pragma unroll
        for (int o = 8; o; o >>= 1) m = fmaxf(m, __shfl_xor_sync(0xffffffffu, m, o, 16));
        float e = (lane < 12) ? expf(logit - m) : 0.f;
        float s = e;
        #pragma unroll
        for (int o = 8; o; o >>= 1) s += __shfl_xor_sync(0xffffffffu, s, o, 16);
        if (lane < 12) s_aw[h * 12 + lane] = e / s;
    }

    if (tid < 96) {
        const int h2 = tid / 12;
        const int rem = tid % 12;
        const int l = rem >> 2;
        const int p = rem & 3;
        const float* rp = &ref_points[((size_t)b * NLVL + l) * 4];
        const size_t obase = (size_t)b * 192 + ((size_t)(h2 * NLVL + l) * NPT + p) * 2;
        float ox = g_off[obase + 0];
        float oy = g_off[obase + 1];
        float lx = rp[0] + ox * 0.125f * rp[2];
        float ly = rp[1] + oy * 0.125f * rp[3];
        const int Wl = (l == 0) ? 80 : (l == 1) ? 40 : 20;
        s_gx[tid] = lx * (float)Wl - 0.5f;
        s_gy[tid] = ly * (float)Wl - 0.5f;
    }
    __syncthreads();

    float acc = 0.f;
    const float* vbase = g_v + (size_t)n * LV * CC + h * HD + lane;

    #pragma unroll
    for (int j = 0; j < 12; j++) {
        const int l = j >> 2;
        const int Wl = (l == 0) ? 80 : (l == 1) ? 40 : 20;
        const int st = (l == 0) ? 0 : (l == 1) ? 6400 : 8000;

        float gx = s_gx[h * 12 + j];
        float gy = s_gy[h * 12 + j];
        float aw = s_aw[h * 12 + j];

        float x0f = floorf(gx), y0f = floorf(gy);
        int x0 = (int)x0f, y0 = (int)y0f;
        float wx = gx - x0f, wy = gy - y0f;

        bool vx0 = (x0 >= 0) && (x0 < Wl);
        bool vx1 = (x0 + 1 >= 0) && (x0 + 1 < Wl);
        bool vy0 = (y0 >= 0) && (y0 < Wl);
        bool vy1 = (y0 + 1 >= 0) && (y0 + 1 < Wl);

        const float* p00 = vbase + ((ptrdiff_t)st + (ptrdiff_t)y0 * Wl + x0) * CC;
        float v00 = (vx0 && vy0) ? p00[0] : 0.f;
        float v01 = (vx1 && vy0) ? p00[CC] : 0.f;
        float v10 = (vx0 && vy1) ? p00[(ptrdiff_t)Wl * CC] : 0.f;
        float v11 = (vx1 && vy1) ? p00[(ptrdiff_t)(Wl + 1) * CC] : 0.f;

        float top = v00 + wx * (v01 - v00);
        float bot = v10 + wx * (v11 - v10);
        acc = fmaf(aw, top + wy * (bot - top), acc);
    }

    out[(size_t)b * CC + h * HD + lane] = acc;
}

// ===========================================================================
// Launch
// ===========================================================================
extern "C" void kernel_launch(void* const* d_in, const int* in_sizes, int n_in,
                              void* d_out, int out_size)
{
    const float* query  = (const float*)d_in[0];
    const float* refp   = (const float*)d_in[1];
    const float* value  = (const float*)d_in[2];
    const float* W_off  = (const float*)d_in[3];
    const float* b_off  = (const float*)d_in[4];
    const float* W_attn = (const float*)d_in[5];
    const float* b_attn = (const float*)d_in[6];
    const float* W_val  = (const float*)d_in[7];
    const float* b_val  = (const float*)d_in[8];
    const float* W_out  = (const float*)d_in[9];
    const float* b_out  = (const float*)d_in[10];
    float* out = (float*)d_out;

    static float *gv = nullptr, *gwt, *goff, *gattn, *gsamp;
    if (!gv) {
        cudaGetSymbolAddress((void**)&gv,    g_v);
        cudaGetSymbolAddress((void**)&gwt,   g_wt);
        cudaGetSymbolAddress((void**)&goff,  g_off);
        cudaGetSymbolAddress((void**)&gattn, g_attn);
        cudaGetSymbolAddress((void**)&gsamp, g_samp);
    }

    const int MQ = NB * LQ;       // 4800
    const int MV = NB * LV;       // 134400

    // 0) W_val^T
    transpose256_kernel<<<dim3(8, 8), dim3(32, 8)>>>(W_val, gwt);

    // 1) value projection via tf32 mma.sync (sm_100-safe tensor path)
    value_mma_kernel<<<dim3(4, MV / 128), 256>>>(value, gwt, b_val, gv);

    // 2) offset logits
    {
        dim3 grid((192 + BN - 1) / BN, (MQ + BM - 1) / BM);
        gemm_bias_kernel<<<grid, 256>>>(query, W_off, b_off, goff, MQ, 192, CC);
    }
    // 3) attention logits
    {
        dim3 grid((96 + BN - 1) / BN, (MQ + BM - 1) / BM);
        gemm_bias_kernel<<<grid, 256>>>(query, W_attn, b_attn, gattn, MQ, 96, CC);
    }
    // 4) fused softmax + locations + bilinear sampling
    msda_sample_kernel<<<MQ, 256>>>(refp, gsamp);

    // 5) output projection
    {
        dim3 grid((CC + BN - 1) / BN, (MQ + BM - 1) / BM);
        gemm_bias_kernel<<<grid, 256>>>(gsamp, W_out, b_out, out, MQ, CC, CC);
    }
}

// round 8
// speedup vs baseline: 2.1475x; 1.2275x over previous
#include <cuda_runtime.h>
#include <cuda_bf16.h>
#include <cstdint>
#include <math.h>

// Problem constants
#define NB    16
#define LQ    300
#define CC    256
#define NHEAD 8
#define NLVL  3
#define NPT   4
#define LV    8400
#define HD    32

// Scratch
__device__ float g_v[(size_t)NB * LV * CC];        // projected value (~137.6 MB)
__device__ float g_wt[(size_t)CC * CC];            // W_val^T (tf32-rounded)
__device__ float g_wq[(size_t)CC * 288];           // [W_off | W_attn] concat
__device__ float g_bq[288];
__device__ float g_q[(size_t)NB * LQ * 288];       // fused off+attn logits
__device__ float g_samp[(size_t)NB * LQ * CC];

__device__ __forceinline__ float tf32_rna(float x) {
    uint32_t r;
    asm("cvt.rna.tf32.f32 %0, %1;" : "=r"(r) : "f"(x));
    return __uint_as_float(r);
}

__device__ __forceinline__ uint32_t smem_u32(const void* p) {
    uint32_t a;
    asm("{ .reg .u64 t; cvta.to.shared.u64 t, %1; cvt.u32.u64 %0, t; }" : "=r"(a) : "l"(p));
    return a;
}

__device__ __forceinline__ void cp16(uint32_t dst, const void* src) {
    asm volatile("cp.async.cg.shared.global [%0], [%1], 16;" :: "r"(dst), "l"(src));
}
__device__ __forceinline__ void cp_commit() {
    asm volatile("cp.async.commit_group;");
}
__device__ __forceinline__ void cp_wait1() {
    asm volatile("cp.async.wait_group 1;");
}
__device__ __forceinline__ void cp_wait0() {
    asm volatile("cp.async.wait_group 0;");
}

__device__ __forceinline__ void mma_tf32_16x8x8(
    float& d0, float& d1, float& d2, float& d3,
    uint32_t a0, uint32_t a1, uint32_t a2, uint32_t a3,
    uint32_t b0, uint32_t b1)
{
    asm volatile(
        "mma.sync.aligned.m16n8k8.row.col.f32.tf32.tf32.f32 "
        "{%0,%1,%2,%3}, {%4,%5,%6,%7}, {%8,%9}, {%0,%1,%2,%3};"
        : "+f"(d0), "+f"(d1), "+f"(d2), "+f"(d3)
        : "r"(a0), "r"(a1), "r"(a2), "r"(a3), "r"(b0), "r"(b1));
}

// ===========================================================================
// W_val transpose + tf32 pre-round: g_wt[n][k] = rna(W_val[k][n])
// ===========================================================================
__global__ void transpose256_kernel(const float* __restrict__ W, float* __restrict__ WT) {
    __shared__ float t[32][33];
    int x = blockIdx.x * 32 + threadIdx.x;
    int y = blockIdx.y * 32 + threadIdx.y;
    #pragma unroll
    for (int j = 0; j < 32; j += 8)
        t[threadIdx.y + j][threadIdx.x] = W[(y + j) * 256 + x];
    __syncthreads();
    x = blockIdx.y * 32 + threadIdx.x;
    y = blockIdx.x * 32 + threadIdx.y;
    #pragma unroll
    for (int j = 0; j < 32; j += 8)
        WT[(y + j) * 256 + x] = tf32_rna(t[threadIdx.x][threadIdx.y + j]);
}

// ===========================================================================
// Concat [W_off | W_attn] -> g_wq (256 x 288), biases -> g_bq (288)
// ===========================================================================
__global__ void prep_qcat_kernel(
    const float* __restrict__ W_off, const float* __restrict__ b_off,
    const float* __restrict__ W_attn, const float* __restrict__ b_attn,
    float* __restrict__ Wq, float* __restrict__ bq)
{
    int idx = blockIdx.x * 256 + threadIdx.x;
    if (idx < 256 * 288) {
        int r = idx / 288, c = idx % 288;
        Wq[idx] = (c < 192) ? W_off[r * 192 + c] : W_attn[r * 96 + (c - 192)];
    }
    if (idx < 288) bq[idx] = (idx < 192) ? b_off[idx] : b_attn[idx - 192];
}

// ===========================================================================
// Value projection: g_v[m][n] = sum_k value[m][k]*W[k][n] + b[n]
// BM=128, BN=256 (full N -> A read ONCE), BK=32, 512 threads (16 warps 4x4),
// warp tile 32x64 (2x8 m16n8k8), cp.async double-buffered.
// Grid: MV/128 = 1050.
// ===========================================================================
#define VST 36                       // padded word stride
#define VA_FLOATS (128 * VST)        // 4608
#define VB_FLOATS (256 * VST)        // 9216
#define VBUF_FLOATS (VA_FLOATS + VB_FLOATS)            // 13824
#define VSMEM_BYTES (2 * VBUF_FLOATS * 4)              // 110592

__global__ __launch_bounds__(512, 1) void value_mma_kernel(
    const float* __restrict__ A,      // value (M x 256)
    const float* __restrict__ WT,     // W^T (256 x 256), pre-rounded
    const float* __restrict__ bias,   // (256)
    float* __restrict__ C)            // g_v (M x 256)
{
    extern __shared__ float smem[];
    const int tid  = threadIdx.x;
    const int lane = tid & 31;
    const int wid  = tid >> 5;
    const int wr   = wid & 3;          // warp row: 4 x 32 rows
    const int wc   = wid >> 2;         // warp col: 4 x 64 cols
    const int gq   = lane >> 2;
    const int tg   = lane & 3;
    const int m0 = blockIdx.x * 128;

    const uint32_t sbase = smem_u32(smem);

    float acc[2][8][4];
    #pragma unroll
    for (int mt = 0; mt < 2; mt++)
        #pragma unroll
        for (int nt = 0; nt < 8; nt++)
            #pragma unroll
            for (int r = 0; r < 4; r++) acc[mt][nt][r] = 0.f;

    // ---- prefetch chunk helper (inlined twice) ----
    #define PREFETCH_CHUNK(cc, buf) do {                                         \
        const int k0_ = (cc) * 32;                                               \
        const uint32_t sA = sbase + (buf) * VBUF_FLOATS * 4;                     \
        const uint32_t sB = sA + VA_FLOATS * 4;                                  \
        _Pragma("unroll")                                                        \
        for (int i = 0; i < 2; i++) {                                            \
            int idx = tid + i * 512;            /* 0..1023 */                    \
            int r = idx >> 3, c4 = idx & 7;                                      \
            cp16(sA + (r * VST + c4 * 4) * 4,                                    \
                 &A[(size_t)(m0 + r) * 256 + k0_ + c4 * 4]);                     \
        }                                                                        \
        _Pragma("unroll")                                                        \
        for (int i = 0; i < 4; i++) {                                            \
            int idx = tid + i * 512;            /* 0..2047 */                    \
            int r = idx >> 3, c4 = idx & 7;                                      \
            cp16(sB + (r * VST + c4 * 4) * 4,                                    \
                 &WT[(size_t)r * 256 + k0_ + c4 * 4]);                           \
        }                                                                        \
        cp_commit();                                                             \
    } while (0)

    PREFETCH_CHUNK(0, 0);

    for (int c = 0; c < 8; c++) {
        const int buf = c & 1;
        if (c < 7) { PREFETCH_CHUNK(c + 1, (c + 1) & 1); cp_wait1(); }
        else       { cp_wait0(); }
        __syncthreads();

        const float* As = smem + buf * VBUF_FLOATS;
        const float* Bs = As + VA_FLOATS;

        #pragma unroll
        for (int kk = 0; kk < 4; kk++) {
            const int kb = kk * 8;
            uint32_t af[2][4];
            #pragma unroll
            for (int mt = 0; mt < 2; mt++) {
                const float* ab = &As[(wr * 32 + mt * 16 + gq) * VST + kb + tg];
                af[mt][0] = __float_as_uint(ab[0]);
                af[mt][1] = __float_as_uint(ab[8 * VST]);
                af[mt][2] = __float_as_uint(ab[4]);
                af[mt][3] = __float_as_uint(ab[8 * VST + 4]);
            }
            uint32_t bf[8][2];
            #pragma unroll
            for (int nt = 0; nt < 8; nt++) {
                const float* bb = &Bs[(wc * 64 + nt * 8 + gq) * VST + kb + tg];
                bf[nt][0] = __float_as_uint(bb[0]);
                bf[nt][1] = __float_as_uint(bb[4]);
            }
            #pragma unroll
            for (int mt = 0; mt < 2; mt++)
                #pragma unroll
                for (int nt = 0; nt < 8; nt++)
                    mma_tf32_16x8x8(acc[mt][nt][0], acc[mt][nt][1],
                                    acc[mt][nt][2], acc[mt][nt][3],
                                    af[mt][0], af[mt][1], af[mt][2], af[mt][3],
                                    bf[nt][0], bf[nt][1]);
        }
        __syncthreads();
    }
    #undef PREFETCH_CHUNK

    // Epilogue
    #pragma unroll
    for (int mt = 0; mt < 2; mt++) {
        #pragma unroll
        for (int nt = 0; nt < 8; nt++) {
            const int col = wc * 64 + nt * 8 + tg * 2;
            const float bx = __ldg(&bias[col]), by = __ldg(&bias[col + 1]);
            const int r0 = m0 + wr * 32 + mt * 16 + gq;
            float2 v0 = make_float2(acc[mt][nt][0] + bx, acc[mt][nt][1] + by);
            float2 v1 = make_float2(acc[mt][nt][2] + bx, acc[mt][nt][3] + by);
            *(float2*)&C[(size_t)r0 * 256 + col]       = v0;
            *(float2*)&C[(size_t)(r0 + 8) * 256 + col] = v1;
        }
    }
}

// ===========================================================================
// Small GEMM: C = A@B + bias. BM=64, BN=64, BK=16, 256 threads, TM=TN=4.
// M must be a multiple of 64 (4800 ok); N multiple of 4.
// ===========================================================================
__global__ __launch_bounds__(256) void gemm_bias_kernel(
    const float* __restrict__ A, const float* __restrict__ B,
    const float* __restrict__ bias, float* __restrict__ C,
    int M, int N, int K)
{
    __shared__ float As[16][68];
    __shared__ float Bs[16][64];

    const int tid = threadIdx.x;
    const int tx = tid & 15;
    const int ty = tid >> 4;
    const int m0 = blockIdx.y * 64;
    const int n0 = blockIdx.x * 64;

    float acc[4][4];
    #pragma unroll
    for (int i = 0; i < 4; i++)
        #pragma unroll
        for (int j = 0; j < 4; j++) acc[i][j] = 0.f;

    for (int k0 = 0; k0 < K; k0 += 16) {
        // A: 64 rows x 16 k = 256 float4 (one per thread), store transposed
        {
            int r = tid >> 2, c4 = (tid & 3) * 4;
            float4 v = *(const float4*)&A[(size_t)(m0 + r) * K + k0 + c4];
            As[c4 + 0][r] = v.x; As[c4 + 1][r] = v.y;
            As[c4 + 2][r] = v.z; As[c4 + 3][r] = v.w;
        }
        // B: 16 rows x 64 cols = 256 float4
        {
            int r = tid >> 4, c4 = (tid & 15) * 4;
            float4 v = make_float4(0.f, 0.f, 0.f, 0.f);
            if (n0 + c4 < N) v = *(const float4*)&B[(size_t)(k0 + r) * N + n0 + c4];
            *(float4*)&Bs[r][c4] = v;
        }
        __syncthreads();
        #pragma unroll
        for (int k = 0; k < 16; k++) {
            float ra[4], rb[4];
            #pragma unroll
            for (int i = 0; i < 4; i++) ra[i] = As[k][ty * 4 + i];
            #pragma unroll
            for (int j = 0; j < 4; j++) rb[j] = Bs[k][tx * 4 + j];
            #pragma unroll
            for (int i = 0; i < 4; i++)
                #pragma unroll
                for (int j = 0; j < 4; j++)
                    acc[i][j] = fmaf(ra[i], rb[j], acc[i][j]);
        }
        __syncthreads();
    }
    const int c = n0 + tx * 4;
    if (c < N) {
        float4 bv = *(const float4*)&bias[c];
        #pragma unroll
        for (int i = 0; i < 4; i++) {
            int r = m0 + ty * 4 + i;
            float4 v;
            v.x = acc[i][0] + bv.x; v.y = acc[i][1] + bv.y;
            v.z = acc[i][2] + bv.z; v.w = acc[i][3] + bv.w;
            *(float4*)&C[(size_t)r * N + c] = v;
        }
    }
}

// ===========================================================================
// Fused softmax + location + bilinear sampling (reads fused g_q: stride 288,
// offsets at [0,192), attn logits at [192,288))
// ===========================================================================
__global__ __launch_bounds__(256) void msda_sample_kernel(
    const float* __restrict__ ref_points, float* __restrict__ out)
{
    const int b = blockIdx.x;
    const int n = b / LQ;
    const int tid = threadIdx.x;
    const int lane = tid & 31;
    const int h = tid >> 5;

    __shared__ float s_aw[96];
    __shared__ float s_gx[96];
    __shared__ float s_gy[96];

    {
        float logit = (lane < 12) ? g_q[(size_t)b * 288 + 192 + h * 12 + lane] : -INFINITY;
        float m = logit;
        #pragma unroll
        for (int o = 8; o; o >>= 1) m = fmaxf(m, __shfl_xor_sync(0xffffffffu, m, o, 16));
        float e = (lane < 12) ? expf(logit - m) : 0.f;
        float s = e;
        #pragma unroll
        for (int o = 8; o; o >>= 1) s += __shfl_xor_sync(0xffffffffu, s, o, 16);
        if (lane < 12) s_aw[h * 12 + lane] = e / s;
    }

    if (tid < 96) {
        const int h2 = tid / 12;
        const int rem = tid % 12;
        const int l = rem >> 2;
        const int p = rem & 3;
        const float* rp = &ref_points[((size_t)b * NLVL + l) * 4];
        const size_t obase = (size_t)b * 288 + ((size_t)(h2 * NLVL + l) * NPT + p) * 2;
        float ox = g_q[obase + 0];
        float oy = g_q[obase + 1];
        float lx = rp[0] + ox * 0.125f * rp[2];
        float ly = rp[1] + oy * 0.125f * rp[3];
        const int Wl = (l == 0) ? 80 : (l == 1) ? 40 : 20;
        s_gx[tid] = lx * (float)Wl - 0.5f;
        s_gy[tid] = ly * (float)Wl - 0.5f;
    }
    __syncthreads();

    float acc = 0.f;
    const float* vbase = g_v + (size_t)n * LV * CC + h * HD + lane;

    #pragma unroll
    for (int j = 0; j < 12; j++) {
        const int l = j >> 2;
        const int Wl = (l == 0) ? 80 : (l == 1) ? 40 : 20;
        const int st = (l == 0) ? 0 : (l == 1) ? 6400 : 8000;

        float gx = s_gx[h * 12 + j];
        float gy = s_gy[h * 12 + j];
        float aw = s_aw[h * 12 + j];

        float x0f = floorf(gx), y0f = floorf(gy);
        int x0 = (int)x0f, y0 = (int)y0f;
        float wx = gx - x0f, wy = gy - y0f;

        bool vx0 = (x0 >= 0) && (x0 < Wl);
        bool vx1 = (x0 + 1 >= 0) && (x0 + 1 < Wl);
        bool vy0 = (y0 >= 0) && (y0 < Wl);
        bool vy1 = (y0 + 1 >= 0) && (y0 + 1 < Wl);

        const float* p00 = vbase + ((ptrdiff_t)st + (ptrdiff_t)y0 * Wl + x0) * CC;
        float v00 = (vx0 && vy0) ? p00[0] : 0.f;
        float v01 = (vx1 && vy0) ? p00[CC] : 0.f;
        float v10 = (vx0 && vy1) ? p00[(ptrdiff_t)Wl * CC] : 0.f;
        float v11 = (vx1 && vy1) ? p00[(ptrdiff_t)(Wl + 1) * CC] : 0.f;

        float top = v00 + wx * (v01 - v00);
        float bot = v10 + wx * (v11 - v10);
        acc = fmaf(aw, top + wy * (bot - top), acc);
    }

    out[(size_t)b * CC + h * HD + lane] = acc;
}

// ===========================================================================
// Launch
// ===========================================================================
extern "C" void kernel_launch(void* const* d_in, const int* in_sizes, int n_in,
                              void* d_out, int out_size)
{
    const float* query  = (const float*)d_in[0];
    const float* refp   = (const float*)d_in[1];
    const float* value  = (const float*)d_in[2];
    const float* W_off  = (const float*)d_in[3];
    const float* b_off  = (const float*)d_in[4];
    const float* W_attn = (const float*)d_in[5];
    const float* b_attn = (const float*)d_in[6];
    const float* W_val  = (const float*)d_in[7];
    const float* b_val  = (const float*)d_in[8];
    const float* W_out  = (const float*)d_in[9];
    const float* b_out  = (const float*)d_in[10];
    float* out = (float*)d_out;

    static float *gv = nullptr, *gwt, *gwq, *gbq, *gq, *gsamp;
    if (!gv) {
        cudaGetSymbolAddress((void**)&gv,    g_v);
        cudaGetSymbolAddress((void**)&gwt,   g_wt);
        cudaGetSymbolAddress((void**)&gwq,   g_wq);
        cudaGetSymbolAddress((void**)&gbq,   g_bq);
        cudaGetSymbolAddress((void**)&gq,    g_q);
        cudaGetSymbolAddress((void**)&gsamp, g_samp);
        cudaFuncSetAttribute(value_mma_kernel,
                             cudaFuncAttributeMaxDynamicSharedMemorySize, VSMEM_BYTES);
    }

    const int MQ = NB * LQ;       // 4800
    const int MV = NB * LV;       // 134400

    // 0) W_val^T (tf32-rounded) + concat query-side weights
    transpose256_kernel<<<dim3(8, 8), dim3(32, 8)>>>(W_val, gwt);
    prep_qcat_kernel<<<288, 256>>>(W_off, b_off, W_attn, b_attn, gwq, gbq);

    // 1) value projection: tf32 mma, A read once, cp.async pipelined
    value_mma_kernel<<<MV / 128, 512, VSMEM_BYTES>>>(value, gwt, b_val, gv);

    // 2) fused offset+attention logits: query @ [W_off|W_attn] + b  (N=288)
    gemm_bias_kernel<<<dim3(5, MQ / 64), 256>>>(query, gwq, gbq, gq, MQ, 288, CC);

    // 3) fused softmax + locations + bilinear sampling
    msda_sample_kernel<<<MQ, 256>>>(refp, gsamp);

    // 4) output projection
    gemm_bias_kernel<<<dim3(4, MQ / 64), 256>>>(gsamp, W_out, b_out, out, MQ, CC, CC);
}